// round 5
// baseline (speedup 1.0000x reference)
#include <cuda_runtime.h>
#include <cuda_bf16.h>
#include <math.h>
#include <stdint.h>

// ---------------------------------------------------------------- constants
#define T_DIM 2048
#define B_DIM 16
#define D_DIM 1024
#define M_DIM (T_DIM * B_DIM)     // 32768
#define BD    (B_DIM * D_DIM)     // 16384
#define NSEG  16
#define SEGT  (T_DIM / NSEG)      // 128

// ---------------------------------------------------------------- scratch
__device__ float g_k[(size_t)M_DIM * D_DIM];              // sigmoid gate
__device__ float g_v[(size_t)M_DIM * D_DIM];              // tanh value
__device__ __nv_bfloat16 g_xh[(size_t)M_DIM * D_DIM];
__device__ __nv_bfloat16 g_xl[(size_t)M_DIM * D_DIM];
__device__ __nv_bfloat16 g_wkh[(size_t)D_DIM * D_DIM];
__device__ __nv_bfloat16 g_wkl[(size_t)D_DIM * D_DIM];
__device__ __nv_bfloat16 g_wvh[(size_t)D_DIM * D_DIM];
__device__ __nv_bfloat16 g_wvl[(size_t)D_DIM * D_DIM];
__device__ float g_segA[NSEG * BD];
__device__ float g_segB[NSEG * BD];
__device__ float g_hstart[NSEG * BD];

__device__ __forceinline__ float fast_sigmoid(float x) {
    return 1.0f / (1.0f + __expf(-x));
}

__device__ __forceinline__ uint32_t smem_u32(const void* p) {
    uint32_t a;
    asm("{ .reg .u64 t; cvta.to.shared.u64 t, %1; cvt.u32.u64 %0, t; }"
        : "=r"(a) : "l"(p));
    return a;
}

// ---------------------------------------------------------------- split
__global__ __launch_bounds__(256)
void split_kernel(const float* __restrict__ src,
                  __nv_bfloat16* __restrict__ hi,
                  __nv_bfloat16* __restrict__ lo, int n4)
{
    int i = blockIdx.x * 256 + threadIdx.x;
    if (i >= n4) return;
    float4 f = ((const float4*)src)[i];
    union { __nv_bfloat16 h[4]; unsigned long long u; } H, L;
    H.h[0] = __float2bfloat16(f.x);
    H.h[1] = __float2bfloat16(f.y);
    H.h[2] = __float2bfloat16(f.z);
    H.h[3] = __float2bfloat16(f.w);
    L.h[0] = __float2bfloat16(f.x - __bfloat162float(H.h[0]));
    L.h[1] = __float2bfloat16(f.y - __bfloat162float(H.h[1]));
    L.h[2] = __float2bfloat16(f.z - __bfloat162float(H.h[2]));
    L.h[3] = __float2bfloat16(f.w - __bfloat162float(H.h[3]));
    ((unsigned long long*)hi)[i] = H.u;
    ((unsigned long long*)lo)[i] = L.u;
}

// ---------------------------------------------------------------- fused GEMM
// One CTA: 128x128 tile of BOTH k and v. K' = 3*1024 split schedule:
//   p0: Ah*Wh   p1: Ah*Wl   p2: Al*Wh
// 512 threads = 16 warps in 4(m) x 4(n); warp tile 32x32 per output.
// 128-wide K chunks, 2-stage cp.async pipeline (depth-1 prefetch).
static constexpr int BM = 128, BN = 128, KCH = 128;
static constexpr int NCH = 3 * D_DIM / KCH;          // 24 chunks
static constexpr int ROWB = KCH * 2 + 16;            // 272 B padded row
static constexpr int A_ST = BM * ROWB;               // 34816 B per tile
static constexpr int STAGE = 3 * A_ST;               // 104448 B (A, Wk, Wv)
static constexpr int NSTG = 2;
static constexpr int SMEM_SZ = NSTG * STAGE;         // 208896 B

#define CP_ASYNC16(dst, src) \
    asm volatile("cp.async.cg.shared.global [%0], [%1], 16;" :: "r"(dst), "l"(src))
#define CP_COMMIT() asm volatile("cp.async.commit_group;" ::: "memory")
#define CP_WAIT1()  asm volatile("cp.async.wait_group 1;" ::: "memory")

#define LDSM_X4(r0, r1, r2, r3, addr) \
    asm volatile("ldmatrix.sync.aligned.m8n8.x4.shared.b16 {%0,%1,%2,%3}, [%4];" \
                 : "=r"(r0), "=r"(r1), "=r"(r2), "=r"(r3) : "r"(addr))

#define MMA_BF16(d, a, b) \
    asm volatile("mma.sync.aligned.m16n8k16.row.col.f32.bf16.bf16.f32 " \
                 "{%0,%1,%2,%3}, {%4,%5,%6,%7}, {%8,%9}, {%0,%1,%2,%3};" \
                 : "+f"((d)[0]), "+f"((d)[1]), "+f"((d)[2]), "+f"((d)[3]) \
                 : "r"((a)[0]), "r"((a)[1]), "r"((a)[2]), "r"((a)[3]),   \
                   "r"((b)[0]), "r"((b)[1]))

__global__ __launch_bounds__(512, 1)
void fused_gemm_kv(const float* __restrict__ bk, const float* __restrict__ bv)
{
    extern __shared__ char smem[];
    const uint32_t sb = smem_u32(smem);
    const int tid = threadIdx.x;
    const int wid = tid >> 5;
    const int lid = tid & 31;
    const int bm = blockIdx.y * BM;
    const int bn = blockIdx.x * BN;

    const int wm0 = (wid & 3) * 32;
    const int wn0 = (wid >> 2) * 32;

    // cp.async mapping: 128 rows x 256 B per tile = 2048 x 16B chunks.
    // 512 threads -> 4 chunks per thread per tile (4 threads per row).
    const int lrow = tid >> 2;           // 0..127
    const int lc0  = tid & 3;            // base 16B chunk

    float acc[2][2][4][4];
    #pragma unroll
    for (int o = 0; o < 2; ++o)
        #pragma unroll
        for (int i = 0; i < 2; ++i)
            #pragma unroll
            for (int j = 0; j < 4; ++j)
                #pragma unroll
                for (int r = 0; r < 4; ++r) acc[o][i][j][r] = 0.0f;

    auto issue_load = [&](int chunk, int buf) {
        const int p  = chunk >> 3;                 // plane pair 0..2 (8 chunks each)
        const int kk = (chunk & 7) * KCH;
        const __nv_bfloat16* Ap = (p == 2) ? g_xl : g_xh;
        const __nv_bfloat16* Kp = (p == 1) ? g_wkl : g_wkh;
        const __nv_bfloat16* Vp = (p == 1) ? g_wvl : g_wvh;
        const uint32_t d0 = sb + buf * STAGE + lrow * ROWB;
        const size_t ga = (size_t)(bm + lrow) * D_DIM + kk;
        const size_t gw = (size_t)(bn + lrow) * D_DIM + kk;
        #pragma unroll
        for (int j = 0; j < 4; ++j) {
            const int c16 = lc0 + j * 4;           // 0..15
            CP_ASYNC16(d0 + c16 * 16,            Ap + ga + c16 * 8);
            CP_ASYNC16(d0 + A_ST + c16 * 16,     Kp + gw + c16 * 8);
            CP_ASYNC16(d0 + 2 * A_ST + c16 * 16, Vp + gw + c16 * 8);
        }
    };

    issue_load(0, 0); CP_COMMIT();
    issue_load(1, 1); CP_COMMIT();

    for (int c = 0; c < NCH; ++c) {
        CP_WAIT1();                 // chunk c resident
        __syncthreads();

        const uint32_t Ab = sb + (c & 1) * STAGE;
        #pragma unroll
        for (int s = 0; s < 8; ++s) {              // eight k16 steps
            uint32_t a[2][4];
            #pragma unroll
            for (int mf = 0; mf < 2; ++mf) {
                uint32_t addr = Ab + (uint32_t)(wm0 + mf * 16 + (lid & 15)) * ROWB
                              + s * 32 + (lid >> 4) * 16;
                LDSM_X4(a[mf][0], a[mf][1], a[mf][2], a[mf][3], addr);
            }
            uint32_t b[2][4][2];
            #pragma unroll
            for (int o = 0; o < 2; ++o) {
                const uint32_t Bb = Ab + (1 + o) * A_ST;
                #pragma unroll
                for (int nf2 = 0; nf2 < 2; ++nf2) {
                    uint32_t addr = Bb
                        + (uint32_t)(wn0 + nf2 * 16 + (lid & 7) + ((lid >> 4) & 1) * 8) * ROWB
                        + s * 32 + ((lid >> 3) & 1) * 16;
                    LDSM_X4(b[o][nf2 * 2][0], b[o][nf2 * 2][1],
                            b[o][nf2 * 2 + 1][0], b[o][nf2 * 2 + 1][1], addr);
                }
            }
            #pragma unroll
            for (int o = 0; o < 2; ++o)
                #pragma unroll
                for (int mf = 0; mf < 2; ++mf)
                    #pragma unroll
                    for (int nf = 0; nf < 4; ++nf)
                        MMA_BF16(acc[o][mf][nf], a[mf], b[o][nf]);
        }

        __syncthreads();            // all reads of buf (c&1) done
        if (c + 2 < NCH) { issue_load(c + 2, c & 1); }
        CP_COMMIT();
    }

    // epilogue: bias + activation, f32x2 stores
    const int grow = lid >> 2;
    const int gcol = (lid & 3) * 2;
    #pragma unroll
    for (int o = 0; o < 2; ++o) {
        float* dst = o ? g_v : g_k;
        const float* bias = o ? bv : bk;
        #pragma unroll
        for (int nf = 0; nf < 4; ++nf) {
            const int col = bn + wn0 + nf * 8 + gcol;
            const float b0 = bias[col], b1 = bias[col + 1];
            #pragma unroll
            for (int mf = 0; mf < 2; ++mf) {
                const int r0 = bm + wm0 + mf * 16 + grow;
                float z0 = acc[o][mf][nf][0] + b0;
                float z1 = acc[o][mf][nf][1] + b1;
                float z2 = acc[o][mf][nf][2] + b0;
                float z3 = acc[o][mf][nf][3] + b1;
                float2 lo_, hi_;
                if (o == 0) {
                    lo_ = make_float2(fast_sigmoid(z0), fast_sigmoid(z1));
                    hi_ = make_float2(fast_sigmoid(z2), fast_sigmoid(z3));
                } else {
                    lo_ = make_float2(tanhf(z0), tanhf(z1));
                    hi_ = make_float2(tanhf(z2), tanhf(z3));
                }
                *(float2*)(dst + (size_t)r0 * D_DIM + col)       = lo_;
                *(float2*)(dst + (size_t)(r0 + 8) * D_DIM + col) = hi_;
            }
        }
    }
}

// ---------------------------------------------------------------- seg scan
// Phase A: per (chain, segment) compose h_out = A*h_in + B over SEGT steps.
__global__ __launch_bounds__(256)
void scanA_kernel()
{
    const int idx = blockIdx.x * 256 + threadIdx.x;   // 0..NSEG*BD-1
    const int i = idx & (BD - 1);
    const int s = idx >> 14;                          // BD = 2^14
    const size_t base = (size_t)(s * SEGT) * BD + i;

    const float* __restrict__ kp = g_k + base;
    const float* __restrict__ vp = g_v + base;

    float A = 1.0f, B = 0.0f;
    constexpr int U = 8;
    float ka[U], va[U], kb[U], vb[U];
    #pragma unroll
    for (int u = 0; u < U; ++u) { ka[u] = kp[(size_t)u * BD]; va[u] = vp[(size_t)u * BD]; }

    for (int j0 = 0; j0 < SEGT; j0 += U) {
        if (j0 + U < SEGT) {
            #pragma unroll
            for (int u = 0; u < U; ++u) {
                kb[u] = kp[(size_t)(j0 + U + u) * BD];
                vb[u] = vp[(size_t)(j0 + U + u) * BD];
            }
        }
        #pragma unroll
        for (int u = 0; u < U; ++u) {
            const float om = 1.0f - ka[u];
            B = om * B + ka[u] * va[u];
            A = om * A;
        }
        #pragma unroll
        for (int u = 0; u < U; ++u) { ka[u] = kb[u]; va[u] = vb[u]; }
    }
    g_segA[idx] = A;
    g_segB[idx] = B;
}

// Phase B: per chain, prefix over the NSEG segments; also write out_h[0].
__global__ __launch_bounds__(128)
void scanB_kernel(const float* __restrict__ h0, float* __restrict__ out_h)
{
    const int i = blockIdx.x * 128 + threadIdx.x;
    float h = h0[i];
    out_h[i] = h;
    #pragma unroll
    for (int s = 0; s < NSEG; ++s) {
        g_hstart[s * BD + i] = h;
        h = g_segA[s * BD + i] * h + g_segB[s * BD + i];
    }
}

// Phase C: replay each segment from h_start, write out_h / out_o.
__global__ __launch_bounds__(256)
void scanC_kernel(float* __restrict__ out_o, float* __restrict__ out_h)
{
    const int idx = blockIdx.x * 256 + threadIdx.x;
    const int i = idx & (BD - 1);
    const int s = idx >> 14;
    const int t0 = s * SEGT;
    const size_t base = (size_t)t0 * BD + i;

    const float* __restrict__ kp = g_k + base;
    const float* __restrict__ vp = g_v + base;
    float* __restrict__ op = out_o + base;
    float* __restrict__ hp = out_h + (size_t)BD + base;

    float h = g_hstart[s * BD + i];
    constexpr int U = 8;
    float ka[U], va[U], kb[U], vb[U];
    #pragma unroll
    for (int u = 0; u < U; ++u) { ka[u] = kp[(size_t)u * BD]; va[u] = vp[(size_t)u * BD]; }

    for (int j0 = 0; j0 < SEGT; j0 += U) {
        if (j0 + U < SEGT) {
            #pragma unroll
            for (int u = 0; u < U; ++u) {
                kb[u] = kp[(size_t)(j0 + U + u) * BD];
                vb[u] = vp[(size_t)(j0 + U + u) * BD];
            }
        }
        #pragma unroll
        for (int u = 0; u < U; ++u) {
            h = (1.0f - ka[u]) * h + ka[u] * va[u];
            hp[(size_t)(j0 + u) * BD] = h;
            float sg = fast_sigmoid(h);
            op[(size_t)(j0 + u) * BD] = h * h * sg;
        }
        #pragma unroll
        for (int u = 0; u < U; ++u) { ka[u] = kb[u]; va[u] = vb[u]; }
    }
}

// ---------------------------------------------------------------- launch
extern "C" void kernel_launch(void* const* d_in, const int* in_sizes, int n_in,
                              void* d_out, int out_size)
{
    const float* x   = (const float*)d_in[0];
    const float* h0  = (const float*)d_in[1];
    const float* W_k = (const float*)d_in[2];
    const float* b_k = (const float*)d_in[3];
    const float* W_v = (const float*)d_in[4];
    const float* b_v = (const float*)d_in[5];

    float* out   = (float*)d_out;
    float* out_o = out;                           // [T, B, D]
    float* out_h = out + (size_t)T_DIM * BD;      // [T+1, B, D]

    __nv_bfloat16 *xh, *xl, *wkh, *wkl, *wvh, *wvl;
    cudaGetSymbolAddress((void**)&xh,  g_xh);
    cudaGetSymbolAddress((void**)&xl,  g_xl);
    cudaGetSymbolAddress((void**)&wkh, g_wkh);
    cudaGetSymbolAddress((void**)&wkl, g_wkl);
    cudaGetSymbolAddress((void**)&wvh, g_wvh);
    cudaGetSymbolAddress((void**)&wvl, g_wvl);

    const int n4x = (M_DIM * D_DIM) / 4;
    const int n4w = (D_DIM * D_DIM) / 4;
    split_kernel<<<(n4x + 255) / 256, 256>>>(x,   xh,  xl,  n4x);
    split_kernel<<<(n4w + 255) / 256, 256>>>(W_k, wkh, wkl, n4w);
    split_kernel<<<(n4w + 255) / 256, 256>>>(W_v, wvh, wvl, n4w);

    cudaFuncSetAttribute(fused_gemm_kv,
                         cudaFuncAttributeMaxDynamicSharedMemorySize, SMEM_SZ);
    dim3 grid(D_DIM / BN, M_DIM / BM);            // (8, 256)
    fused_gemm_kv<<<grid, 512, SMEM_SZ>>>(b_k, b_v);

    scanA_kernel<<<(NSEG * BD) / 256, 256>>>();
    scanB_kernel<<<BD / 128, 128>>>(h0, out_h);
    scanC_kernel<<<(NSEG * BD) / 256, 256>>>(out_o, out_h);
}

// round 6
// speedup vs baseline: 1.1021x; 1.1021x over previous
#include <cuda_runtime.h>
#include <cuda_bf16.h>
#include <math.h>
#include <stdint.h>

// ---------------------------------------------------------------- constants
#define T_DIM 2048
#define B_DIM 16
#define D_DIM 1024
#define M_DIM (T_DIM * B_DIM)     // 32768
#define BD    (B_DIM * D_DIM)     // 16384
#define NSEG  16
#define SEGT  (T_DIM / NSEG)      // 128

// ---------------------------------------------------------------- scratch
__device__ float g_k[(size_t)M_DIM * D_DIM];              // sigmoid gate
__device__ float g_v[(size_t)M_DIM * D_DIM];              // tanh value
__device__ __nv_bfloat16 g_xh[(size_t)M_DIM * D_DIM];
__device__ __nv_bfloat16 g_xl[(size_t)M_DIM * D_DIM];
__device__ __nv_bfloat16 g_wkh[(size_t)D_DIM * D_DIM];
__device__ __nv_bfloat16 g_wkl[(size_t)D_DIM * D_DIM];
__device__ __nv_bfloat16 g_wvh[(size_t)D_DIM * D_DIM];
__device__ __nv_bfloat16 g_wvl[(size_t)D_DIM * D_DIM];
__device__ float g_segA[NSEG * BD];
__device__ float g_segB[NSEG * BD];
__device__ float g_hstart[NSEG * BD];

__device__ __forceinline__ float fast_sigmoid(float x) {
    return 1.0f / (1.0f + __expf(-x));
}

__device__ __forceinline__ uint32_t smem_u32(const void* p) {
    uint32_t a;
    asm("{ .reg .u64 t; cvta.to.shared.u64 t, %1; cvt.u32.u64 %0, t; }"
        : "=r"(a) : "l"(p));
    return a;
}

// ---------------------------------------------------------------- split
__global__ __launch_bounds__(256)
void split_kernel(const float* __restrict__ src,
                  __nv_bfloat16* __restrict__ hi,
                  __nv_bfloat16* __restrict__ lo, int n4)
{
    int i = blockIdx.x * 256 + threadIdx.x;
    if (i >= n4) return;
    float4 f = ((const float4*)src)[i];
    union { __nv_bfloat16 h[4]; unsigned long long u; } H, L;
    H.h[0] = __float2bfloat16(f.x);
    H.h[1] = __float2bfloat16(f.y);
    H.h[2] = __float2bfloat16(f.z);
    H.h[3] = __float2bfloat16(f.w);
    L.h[0] = __float2bfloat16(f.x - __bfloat162float(H.h[0]));
    L.h[1] = __float2bfloat16(f.y - __bfloat162float(H.h[1]));
    L.h[2] = __float2bfloat16(f.z - __bfloat162float(H.h[2]));
    L.h[3] = __float2bfloat16(f.w - __bfloat162float(H.h[3]));
    ((unsigned long long*)hi)[i] = H.u;
    ((unsigned long long*)lo)[i] = L.u;
}

// ---------------------------------------------------------------- fused GEMM
// R4 structure (best measured): KCH=64, 3-stage cp.async pipeline, ONE
// __syncthreads per chunk. NEW: intra-chunk register double-buffering of
// ldmatrix fragments so LDSM latency overlaps MMA issue.
static constexpr int BM = 128, BN = 128, KCH = 64;
static constexpr int NCH = 3 * D_DIM / KCH;          // 48 chunks
static constexpr int ROWB = KCH * 2 + 16;            // 144 B padded row
static constexpr int A_ST = BM * ROWB;               // 18432 B per tile
static constexpr int STAGE = 3 * A_ST;               // 55296 B (A, Wk, Wv)
static constexpr int NSTG = 3;
static constexpr int SMEM_SZ = NSTG * STAGE;         // 165888 B

#define CP_ASYNC16(dst, src) \
    asm volatile("cp.async.cg.shared.global [%0], [%1], 16;" :: "r"(dst), "l"(src))
#define CP_COMMIT() asm volatile("cp.async.commit_group;" ::: "memory")
#define CP_WAIT1()  asm volatile("cp.async.wait_group 1;" ::: "memory")

#define LDSM_X4(r0, r1, r2, r3, addr) \
    asm volatile("ldmatrix.sync.aligned.m8n8.x4.shared.b16 {%0,%1,%2,%3}, [%4];" \
                 : "=r"(r0), "=r"(r1), "=r"(r2), "=r"(r3) : "r"(addr))

#define MMA_BF16(d, a, b) \
    asm volatile("mma.sync.aligned.m16n8k16.row.col.f32.bf16.bf16.f32 " \
                 "{%0,%1,%2,%3}, {%4,%5,%6,%7}, {%8,%9}, {%0,%1,%2,%3};" \
                 : "+f"((d)[0]), "+f"((d)[1]), "+f"((d)[2]), "+f"((d)[3]) \
                 : "r"((a)[0]), "r"((a)[1]), "r"((a)[2]), "r"((a)[3]),   \
                   "r"((b)[0]), "r"((b)[1]))

__global__ __launch_bounds__(512, 1)
void fused_gemm_kv(const float* __restrict__ bk, const float* __restrict__ bv)
{
    extern __shared__ char smem[];
    const uint32_t sb = smem_u32(smem);
    const int tid = threadIdx.x;
    const int wid = tid >> 5;
    const int lid = tid & 31;
    const int bm = blockIdx.y * BM;
    const int bn = blockIdx.x * BN;

    const int wm0 = (wid & 3) * 32;
    const int wn0 = (wid >> 2) * 32;

    // cp.async mapping: 128 rows x 128 B = 1024 x 16B chunks; 2 per thread
    const int lrow0 = tid >> 3;          // rows 0..63  (t=0)
    const int lc16  = tid & 7;           // 16B column chunk 0..7

    float acc[2][2][4][4];
    #pragma unroll
    for (int o = 0; o < 2; ++o)
        #pragma unroll
        for (int i = 0; i < 2; ++i)
            #pragma unroll
            for (int j = 0; j < 4; ++j)
                #pragma unroll
                for (int r = 0; r < 4; ++r) acc[o][i][j][r] = 0.0f;

    // precomputed per-thread ldmatrix address components
    const uint32_t a_row_off = (uint32_t)(wm0 + (lid & 15)) * ROWB + (lid >> 4) * 16;
    const uint32_t b_row_off = (uint32_t)(wn0 + (lid & 7) + ((lid >> 4) & 1) * 8) * ROWB
                             + ((lid >> 3) & 1) * 16;

    auto issue_load = [&](int chunk, int buf) {
        const int p  = chunk >> 4;                 // plane pair 0..2 (16 chunks each)
        const int kk = (chunk & 15) * KCH;
        const __nv_bfloat16* Ap = (p == 2) ? g_xl : g_xh;
        const __nv_bfloat16* Kp = (p == 1) ? g_wkl : g_wkh;
        const __nv_bfloat16* Vp = (p == 1) ? g_wvl : g_wvh;
        #pragma unroll
        for (int t = 0; t < 2; ++t) {
            const int r = lrow0 + t * 64;
            const uint32_t d0 = sb + buf * STAGE + r * ROWB + lc16 * 16;
            CP_ASYNC16(d0,            Ap + (size_t)(bm + r) * D_DIM + kk + lc16 * 8);
            CP_ASYNC16(d0 + A_ST,     Kp + (size_t)(bn + r) * D_DIM + kk + lc16 * 8);
            CP_ASYNC16(d0 + 2 * A_ST, Vp + (size_t)(bn + r) * D_DIM + kk + lc16 * 8);
        }
    };

    // fragment loader for k16-step s from stage base Ab
    auto ldfrag = [&](uint32_t Ab, int s,
                      uint32_t (&a)[2][4], uint32_t (&b)[2][4][2]) {
        #pragma unroll
        for (int mf = 0; mf < 2; ++mf) {
            uint32_t addr = Ab + a_row_off + (uint32_t)mf * 16 * ROWB + s * 32;
            LDSM_X4(a[mf][0], a[mf][1], a[mf][2], a[mf][3], addr);
        }
        #pragma unroll
        for (int o = 0; o < 2; ++o) {
            const uint32_t Bb = Ab + (1 + o) * A_ST;
            #pragma unroll
            for (int nf2 = 0; nf2 < 2; ++nf2) {
                uint32_t addr = Bb + b_row_off + (uint32_t)nf2 * 16 * ROWB + s * 32;
                LDSM_X4(b[o][nf2 * 2][0], b[o][nf2 * 2][1],
                        b[o][nf2 * 2 + 1][0], b[o][nf2 * 2 + 1][1], addr);
            }
        }
    };

    issue_load(0, 0); CP_COMMIT();
    issue_load(1, 1); CP_COMMIT();

    uint32_t aR[2][2][4];       // [buf][mf][4]
    uint32_t bR[2][2][4][2];    // [buf][o][nf][2]

    int buf_c = 0, buf_n = 2;
    for (int c = 0; c < NCH; ++c) {
        CP_WAIT1();
        __syncthreads();
        // safe: buffer buf_n == (c-1)%3 finished being read before the barrier
        if (c + 2 < NCH) issue_load(c + 2, buf_n);
        CP_COMMIT();

        const uint32_t Ab = sb + buf_c * STAGE;
        buf_n = buf_c;
        buf_c = (buf_c + 1 == 3) ? 0 : buf_c + 1;

        ldfrag(Ab, 0, aR[0], bR[0]);
        #pragma unroll
        for (int s = 0; s < 4; ++s) {
            const int cur = s & 1, nxt = cur ^ 1;
            if (s < 3) ldfrag(Ab, s + 1, aR[nxt], bR[nxt]);
            #pragma unroll
            for (int o = 0; o < 2; ++o)
                #pragma unroll
                for (int mf = 0; mf < 2; ++mf)
                    #pragma unroll
                    for (int nf = 0; nf < 4; ++nf)
                        MMA_BF16(acc[o][mf][nf], aR[cur][mf], bR[cur][o][nf]);
        }
    }

    // epilogue: bias + activation, f32x2 stores
    const int grow = lid >> 2;
    const int gcol = (lid & 3) * 2;
    #pragma unroll
    for (int o = 0; o < 2; ++o) {
        float* dst = o ? g_v : g_k;
        const float* bias = o ? bv : bk;
        #pragma unroll
        for (int nf = 0; nf < 4; ++nf) {
            const int col = bn + wn0 + nf * 8 + gcol;
            const float b0 = bias[col], b1 = bias[col + 1];
            #pragma unroll
            for (int mf = 0; mf < 2; ++mf) {
                const int r0 = bm + wm0 + mf * 16 + grow;
                float z0 = acc[o][mf][nf][0] + b0;
                float z1 = acc[o][mf][nf][1] + b1;
                float z2 = acc[o][mf][nf][2] + b0;
                float z3 = acc[o][mf][nf][3] + b1;
                float2 lo_, hi_;
                if (o == 0) {
                    lo_ = make_float2(fast_sigmoid(z0), fast_sigmoid(z1));
                    hi_ = make_float2(fast_sigmoid(z2), fast_sigmoid(z3));
                } else {
                    lo_ = make_float2(tanhf(z0), tanhf(z1));
                    hi_ = make_float2(tanhf(z2), tanhf(z3));
                }
                *(float2*)(dst + (size_t)r0 * D_DIM + col)       = lo_;
                *(float2*)(dst + (size_t)(r0 + 8) * D_DIM + col) = hi_;
            }
        }
    }
}

// ---------------------------------------------------------------- seg scan
__global__ __launch_bounds__(256)
void scanA_kernel()
{
    const int idx = blockIdx.x * 256 + threadIdx.x;   // 0..NSEG*BD-1
    const int i = idx & (BD - 1);
    const int s = idx >> 14;                          // BD = 2^14
    const size_t base = (size_t)(s * SEGT) * BD + i;

    const float* __restrict__ kp = g_k + base;
    const float* __restrict__ vp = g_v + base;

    float A = 1.0f, B = 0.0f;
    constexpr int U = 8;
    float ka[U], va[U], kb[U], vb[U];
    #pragma unroll
    for (int u = 0; u < U; ++u) { ka[u] = kp[(size_t)u * BD]; va[u] = vp[(size_t)u * BD]; }

    for (int j0 = 0; j0 < SEGT; j0 += U) {
        if (j0 + U < SEGT) {
            #pragma unroll
            for (int u = 0; u < U; ++u) {
                kb[u] = kp[(size_t)(j0 + U + u) * BD];
                vb[u] = vp[(size_t)(j0 + U + u) * BD];
            }
        }
        #pragma unroll
        for (int u = 0; u < U; ++u) {
            const float om = 1.0f - ka[u];
            B = om * B + ka[u] * va[u];
            A = om * A;
        }
        #pragma unroll
        for (int u = 0; u < U; ++u) { ka[u] = kb[u]; va[u] = vb[u]; }
    }
    g_segA[idx] = A;
    g_segB[idx] = B;
}

__global__ __launch_bounds__(128)
void scanB_kernel(const float* __restrict__ h0, float* __restrict__ out_h)
{
    const int i = blockIdx.x * 128 + threadIdx.x;
    float h = h0[i];
    out_h[i] = h;
    #pragma unroll
    for (int s = 0; s < NSEG; ++s) {
        g_hstart[s * BD + i] = h;
        h = g_segA[s * BD + i] * h + g_segB[s * BD + i];
    }
}

__global__ __launch_bounds__(256)
void scanC_kernel(float* __restrict__ out_o, float* __restrict__ out_h)
{
    const int idx = blockIdx.x * 256 + threadIdx.x;
    const int i = idx & (BD - 1);
    const int s = idx >> 14;
    const int t0 = s * SEGT;
    const size_t base = (size_t)t0 * BD + i;

    const float* __restrict__ kp = g_k + base;
    const float* __restrict__ vp = g_v + base;
    float* __restrict__ op = out_o + base;
    float* __restrict__ hp = out_h + (size_t)BD + base;

    float h = g_hstart[s * BD + i];
    constexpr int U = 8;
    float ka[U], va[U], kb[U], vb[U];
    #pragma unroll
    for (int u = 0; u < U; ++u) { ka[u] = kp[(size_t)u * BD]; va[u] = vp[(size_t)u * BD]; }

    for (int j0 = 0; j0 < SEGT; j0 += U) {
        if (j0 + U < SEGT) {
            #pragma unroll
            for (int u = 0; u < U; ++u) {
                kb[u] = kp[(size_t)(j0 + U + u) * BD];
                vb[u] = vp[(size_t)(j0 + U + u) * BD];
            }
        }
        #pragma unroll
        for (int u = 0; u < U; ++u) {
            h = (1.0f - ka[u]) * h + ka[u] * va[u];
            hp[(size_t)(j0 + u) * BD] = h;
            float sg = fast_sigmoid(h);
            op[(size_t)(j0 + u) * BD] = h * h * sg;
        }
        #pragma unroll
        for (int u = 0; u < U; ++u) { ka[u] = kb[u]; va[u] = vb[u]; }
    }
}

// ---------------------------------------------------------------- launch
extern "C" void kernel_launch(void* const* d_in, const int* in_sizes, int n_in,
                              void* d_out, int out_size)
{
    const float* x   = (const float*)d_in[0];
    const float* h0  = (const float*)d_in[1];
    const float* W_k = (const float*)d_in[2];
    const float* b_k = (const float*)d_in[3];
    const float* W_v = (const float*)d_in[4];
    const float* b_v = (const float*)d_in[5];

    float* out   = (float*)d_out;
    float* out_o = out;                           // [T, B, D]
    float* out_h = out + (size_t)T_DIM * BD;      // [T+1, B, D]

    __nv_bfloat16 *xh, *xl, *wkh, *wkl, *wvh, *wvl;
    cudaGetSymbolAddress((void**)&xh,  g_xh);
    cudaGetSymbolAddress((void**)&xl,  g_xl);
    cudaGetSymbolAddress((void**)&wkh, g_wkh);
    cudaGetSymbolAddress((void**)&wkl, g_wkl);
    cudaGetSymbolAddress((void**)&wvh, g_wvh);
    cudaGetSymbolAddress((void**)&wvl, g_wvl);

    const int n4x = (M_DIM * D_DIM) / 4;
    const int n4w = (D_DIM * D_DIM) / 4;
    split_kernel<<<(n4x + 255) / 256, 256>>>(x,   xh,  xl,  n4x);
    split_kernel<<<(n4w + 255) / 256, 256>>>(W_k, wkh, wkl, n4w);
    split_kernel<<<(n4w + 255) / 256, 256>>>(W_v, wvh, wvl, n4w);

    cudaFuncSetAttribute(fused_gemm_kv,
                         cudaFuncAttributeMaxDynamicSharedMemorySize, SMEM_SZ);
    dim3 grid(D_DIM / BN, M_DIM / BM);            // (8, 256)
    fused_gemm_kv<<<grid, 512, SMEM_SZ>>>(b_k, b_v);

    scanA_kernel<<<(NSEG * BD) / 256, 256>>>();
    scanB_kernel<<<BD / 128, 128>>>(h0, out_h);
    scanC_kernel<<<(NSEG * BD) / 256, 256>>>(out_o, out_h);
}

// round 7
// speedup vs baseline: 1.2169x; 1.1041x over previous
#include <cuda_runtime.h>
#include <cuda_bf16.h>
#include <math.h>
#include <stdint.h>

// ---------------------------------------------------------------- constants
#define T_DIM 2048
#define B_DIM 16
#define D_DIM 1024
#define M_DIM (T_DIM * B_DIM)     // 32768
#define BD    (B_DIM * D_DIM)     // 16384
#define NSEG  16
#define SEGT  (T_DIM / NSEG)      // 128

// ---------------------------------------------------------------- scratch
__device__ float g_k[(size_t)M_DIM * D_DIM];              // sigmoid gate
__device__ float g_v[(size_t)M_DIM * D_DIM];              // tanh value
__device__ __nv_bfloat16 g_xh[(size_t)M_DIM * D_DIM];
__device__ __nv_bfloat16 g_xl[(size_t)M_DIM * D_DIM];
__device__ __nv_bfloat16 g_wkh[(size_t)D_DIM * D_DIM];
__device__ __nv_bfloat16 g_wkl[(size_t)D_DIM * D_DIM];
__device__ __nv_bfloat16 g_wvh[(size_t)D_DIM * D_DIM];
__device__ __nv_bfloat16 g_wvl[(size_t)D_DIM * D_DIM];
__device__ float g_segA[NSEG * BD];
__device__ float g_segB[NSEG * BD];
__device__ float g_hstart[NSEG * BD];

__device__ __forceinline__ float fast_sigmoid(float x) {
    return 1.0f / (1.0f + __expf(-x));
}

__device__ __forceinline__ uint32_t smem_u32(const void* p) {
    uint32_t a;
    asm("{ .reg .u64 t; cvta.to.shared.u64 t, %1; cvt.u32.u64 %0, t; }"
        : "=r"(a) : "l"(p));
    return a;
}

// ---------------------------------------------------------------- split
__global__ __launch_bounds__(256)
void split_kernel(const float* __restrict__ src,
                  __nv_bfloat16* __restrict__ hi,
                  __nv_bfloat16* __restrict__ lo, int n4)
{
    int i = blockIdx.x * 256 + threadIdx.x;
    if (i >= n4) return;
    float4 f = ((const float4*)src)[i];
    union { __nv_bfloat16 h[4]; unsigned long long u; } H, L;
    H.h[0] = __float2bfloat16(f.x);
    H.h[1] = __float2bfloat16(f.y);
    H.h[2] = __float2bfloat16(f.z);
    H.h[3] = __float2bfloat16(f.w);
    L.h[0] = __float2bfloat16(f.x - __bfloat162float(H.h[0]));
    L.h[1] = __float2bfloat16(f.y - __bfloat162float(H.h[1]));
    L.h[2] = __float2bfloat16(f.z - __bfloat162float(H.h[2]));
    L.h[3] = __float2bfloat16(f.w - __bfloat162float(H.h[3]));
    ((unsigned long long*)hi)[i] = H.u;
    ((unsigned long long*)lo)[i] = L.u;
}

// ---------------------------------------------------------------- fused GEMM
// 2 CTAs/SM: 256 threads, tile BM=128 x BN=64 of BOTH k and v.
// K' = 3*1024 split schedule (p0: Ah*Wh, p1: Ah*Wl, p2: Al*Wh).
// 8 warps = 4(m) x 2(n); warp tile 32x32 per output.
// KCH=64, 3-stage cp.async pipeline, ONE __syncthreads per chunk (R4 schedule).
static constexpr int BM = 128, BN = 64, KCH = 64;
static constexpr int NCH = 3 * D_DIM / KCH;          // 48 chunks
static constexpr int ROWB = KCH * 2 + 16;            // 144 B padded row
static constexpr int A_ST = BM * ROWB;               // 18432 B (A tile)
static constexpr int W_ST = BN * ROWB;               // 9216 B  (per W tile)
static constexpr int STAGE = A_ST + 2 * W_ST;        // 36864 B
static constexpr int NSTG = 3;
static constexpr int SMEM_SZ = NSTG * STAGE;         // 110592 B

#define CP_ASYNC16(dst, src) \
    asm volatile("cp.async.cg.shared.global [%0], [%1], 16;" :: "r"(dst), "l"(src))
#define CP_COMMIT() asm volatile("cp.async.commit_group;" ::: "memory")
#define CP_WAIT1()  asm volatile("cp.async.wait_group 1;" ::: "memory")

#define LDSM_X4(r0, r1, r2, r3, addr) \
    asm volatile("ldmatrix.sync.aligned.m8n8.x4.shared.b16 {%0,%1,%2,%3}, [%4];" \
                 : "=r"(r0), "=r"(r1), "=r"(r2), "=r"(r3) : "r"(addr))

#define MMA_BF16(d, a, b) \
    asm volatile("mma.sync.aligned.m16n8k16.row.col.f32.bf16.bf16.f32 " \
                 "{%0,%1,%2,%3}, {%4,%5,%6,%7}, {%8,%9}, {%0,%1,%2,%3};" \
                 : "+f"((d)[0]), "+f"((d)[1]), "+f"((d)[2]), "+f"((d)[3]) \
                 : "r"((a)[0]), "r"((a)[1]), "r"((a)[2]), "r"((a)[3]),   \
                   "r"((b)[0]), "r"((b)[1]))

__global__ __launch_bounds__(256, 2)
void fused_gemm_kv(const float* __restrict__ bk, const float* __restrict__ bv)
{
    extern __shared__ char smem[];
    const uint32_t sb = smem_u32(smem);
    const int tid = threadIdx.x;
    const int wid = tid >> 5;          // 0..7
    const int lid = tid & 31;
    const int bm = blockIdx.y * BM;
    const int bn = blockIdx.x * BN;

    const int wm0 = (wid & 3) * 32;    // 0..96
    const int wn0 = (wid >> 2) * 32;   // 0 or 32

    float acc[2][2][4][4];
    #pragma unroll
    for (int o = 0; o < 2; ++o)
        #pragma unroll
        for (int i = 0; i < 2; ++i)
            #pragma unroll
            for (int j = 0; j < 4; ++j)
                #pragma unroll
                for (int r = 0; r < 4; ++r) acc[o][i][j][r] = 0.0f;

    // per-thread ldmatrix address components
    const uint32_t a_row_off = (uint32_t)(wm0 + (lid & 15)) * ROWB + (lid >> 4) * 16;
    const uint32_t b_row_off = (uint32_t)(wn0 + (lid & 7) + ((lid >> 4) & 1) * 8) * ROWB
                             + ((lid >> 3) & 1) * 16;

    // cp.async: 2048 16B-chunks per stage (A:1024, Wk:512, Wv:512); 8/thread
    auto issue_load = [&](int chunk, int buf) {
        const int p  = chunk >> 4;                 // plane pair 0..2 (16 chunks each)
        const int kk = (chunk & 15) * KCH;
        const __nv_bfloat16* Ap = (p == 2) ? g_xl : g_xh;
        const __nv_bfloat16* Kp = (p == 1) ? g_wkl : g_wkh;
        const __nv_bfloat16* Vp = (p == 1) ? g_wvl : g_wvh;
        const uint32_t base = sb + buf * STAGE;
        // A tile: idx 0..1023
        #pragma unroll
        for (int j = 0; j < 4; ++j) {
            const int idx = tid + j * 256;
            const int r = idx >> 3, c = idx & 7;
            CP_ASYNC16(base + r * ROWB + c * 16,
                       Ap + (size_t)(bm + r) * D_DIM + kk + c * 8);
        }
        // W tiles: idx 0..1023 -> (w, r, c)
        #pragma unroll
        for (int j = 0; j < 4; ++j) {
            const int idx = tid + j * 256;
            const int w = idx >> 9;                // 0 = Wk, 1 = Wv
            const int r = (idx >> 3) & 63, c = idx & 7;
            const __nv_bfloat16* Wp = w ? Vp : Kp;
            CP_ASYNC16(base + A_ST + w * W_ST + r * ROWB + c * 16,
                       Wp + (size_t)(bn + r) * D_DIM + kk + c * 8);
        }
    };

    issue_load(0, 0); CP_COMMIT();
    issue_load(1, 1); CP_COMMIT();

    int buf_c = 0, buf_n = 2;
    for (int c = 0; c < NCH; ++c) {
        CP_WAIT1();
        __syncthreads();
        // safe: buffer buf_n == (c-1)%3 finished being read before the barrier
        if (c + 2 < NCH) issue_load(c + 2, buf_n);
        CP_COMMIT();

        const uint32_t Ab = sb + buf_c * STAGE;
        buf_n = buf_c;
        buf_c = (buf_c + 1 == 3) ? 0 : buf_c + 1;

        #pragma unroll
        for (int s = 0; s < 4; ++s) {              // four k16 steps
            uint32_t a[2][4];
            #pragma unroll
            for (int mf = 0; mf < 2; ++mf) {
                uint32_t addr = Ab + a_row_off + (uint32_t)mf * 16 * ROWB + s * 32;
                LDSM_X4(a[mf][0], a[mf][1], a[mf][2], a[mf][3], addr);
            }
            uint32_t b[2][4][2];
            #pragma unroll
            for (int o = 0; o < 2; ++o) {
                const uint32_t Bb = Ab + A_ST + o * W_ST;
                #pragma unroll
                for (int nf2 = 0; nf2 < 2; ++nf2) {
                    uint32_t addr = Bb + b_row_off + (uint32_t)nf2 * 16 * ROWB + s * 32;
                    LDSM_X4(b[o][nf2 * 2][0], b[o][nf2 * 2][1],
                            b[o][nf2 * 2 + 1][0], b[o][nf2 * 2 + 1][1], addr);
                }
            }
            #pragma unroll
            for (int o = 0; o < 2; ++o)
                #pragma unroll
                for (int mf = 0; mf < 2; ++mf)
                    #pragma unroll
                    for (int nf = 0; nf < 4; ++nf)
                        MMA_BF16(acc[o][mf][nf], a[mf], b[o][nf]);
        }
    }

    // epilogue: bias + activation, f32x2 stores
    const int grow = lid >> 2;
    const int gcol = (lid & 3) * 2;
    #pragma unroll
    for (int o = 0; o < 2; ++o) {
        float* dst = o ? g_v : g_k;
        const float* bias = o ? bv : bk;
        #pragma unroll
        for (int nf = 0; nf < 4; ++nf) {
            const int col = bn + wn0 + nf * 8 + gcol;
            const float b0 = bias[col], b1 = bias[col + 1];
            #pragma unroll
            for (int mf = 0; mf < 2; ++mf) {
                const int r0 = bm + wm0 + mf * 16 + grow;
                float z0 = acc[o][mf][nf][0] + b0;
                float z1 = acc[o][mf][nf][1] + b1;
                float z2 = acc[o][mf][nf][2] + b0;
                float z3 = acc[o][mf][nf][3] + b1;
                float2 lo_, hi_;
                if (o == 0) {
                    lo_ = make_float2(fast_sigmoid(z0), fast_sigmoid(z1));
                    hi_ = make_float2(fast_sigmoid(z2), fast_sigmoid(z3));
                } else {
                    lo_ = make_float2(tanhf(z0), tanhf(z1));
                    hi_ = make_float2(tanhf(z2), tanhf(z3));
                }
                *(float2*)(dst + (size_t)r0 * D_DIM + col)       = lo_;
                *(float2*)(dst + (size_t)(r0 + 8) * D_DIM + col) = hi_;
            }
        }
    }
}

// ---------------------------------------------------------------- seg scan
__global__ __launch_bounds__(256)
void scanA_kernel()
{
    const int idx = blockIdx.x * 256 + threadIdx.x;   // 0..NSEG*BD-1
    const int i = idx & (BD - 1);
    const int s = idx >> 14;                          // BD = 2^14
    const size_t base = (size_t)(s * SEGT) * BD + i;

    const float* __restrict__ kp = g_k + base;
    const float* __restrict__ vp = g_v + base;

    float A = 1.0f, B = 0.0f;
    constexpr int U = 8;
    float ka[U], va[U], kb[U], vb[U];
    #pragma unroll
    for (int u = 0; u < U; ++u) { ka[u] = kp[(size_t)u * BD]; va[u] = vp[(size_t)u * BD]; }

    for (int j0 = 0; j0 < SEGT; j0 += U) {
        if (j0 + U < SEGT) {
            #pragma unroll
            for (int u = 0; u < U; ++u) {
                kb[u] = kp[(size_t)(j0 + U + u) * BD];
                vb[u] = vp[(size_t)(j0 + U + u) * BD];
            }
        }
        #pragma unroll
        for (int u = 0; u < U; ++u) {
            const float om = 1.0f - ka[u];
            B = om * B + ka[u] * va[u];
            A = om * A;
        }
        #pragma unroll
        for (int u = 0; u < U; ++u) { ka[u] = kb[u]; va[u] = vb[u]; }
    }
    g_segA[idx] = A;
    g_segB[idx] = B;
}

__global__ __launch_bounds__(128)
void scanB_kernel(const float* __restrict__ h0, float* __restrict__ out_h)
{
    const int i = blockIdx.x * 128 + threadIdx.x;
    float h = h0[i];
    out_h[i] = h;
    #pragma unroll
    for (int s = 0; s < NSEG; ++s) {
        g_hstart[s * BD + i] = h;
        h = g_segA[s * BD + i] * h + g_segB[s * BD + i];
    }
}

__global__ __launch_bounds__(256)
void scanC_kernel(float* __restrict__ out_o, float* __restrict__ out_h)
{
    const int idx = blockIdx.x * 256 + threadIdx.x;
    const int i = idx & (BD - 1);
    const int s = idx >> 14;
    const int t0 = s * SEGT;
    const size_t base = (size_t)t0 * BD + i;

    const float* __restrict__ kp = g_k + base;
    const float* __restrict__ vp = g_v + base;
    float* __restrict__ op = out_o + base;
    float* __restrict__ hp = out_h + (size_t)BD + base;

    float h = g_hstart[s * BD + i];
    constexpr int U = 8;
    float ka[U], va[U], kb[U], vb[U];
    #pragma unroll
    for (int u = 0; u < U; ++u) { ka[u] = kp[(size_t)u * BD]; va[u] = vp[(size_t)u * BD]; }

    for (int j0 = 0; j0 < SEGT; j0 += U) {
        if (j0 + U < SEGT) {
            #pragma unroll
            for (int u = 0; u < U; ++u) {
                kb[u] = kp[(size_t)(j0 + U + u) * BD];
                vb[u] = vp[(size_t)(j0 + U + u) * BD];
            }
        }
        #pragma unroll
        for (int u = 0; u < U; ++u) {
            h = (1.0f - ka[u]) * h + ka[u] * va[u];
            hp[(size_t)(j0 + u) * BD] = h;
            float sg = fast_sigmoid(h);
            op[(size_t)(j0 + u) * BD] = h * h * sg;
        }
        #pragma unroll
        for (int u = 0; u < U; ++u) { ka[u] = kb[u]; va[u] = vb[u]; }
    }
}

// ---------------------------------------------------------------- launch
extern "C" void kernel_launch(void* const* d_in, const int* in_sizes, int n_in,
                              void* d_out, int out_size)
{
    const float* x   = (const float*)d_in[0];
    const float* h0  = (const float*)d_in[1];
    const float* W_k = (const float*)d_in[2];
    const float* b_k = (const float*)d_in[3];
    const float* W_v = (const float*)d_in[4];
    const float* b_v = (const float*)d_in[5];

    float* out   = (float*)d_out;
    float* out_o = out;                           // [T, B, D]
    float* out_h = out + (size_t)T_DIM * BD;      // [T+1, B, D]

    __nv_bfloat16 *xh, *xl, *wkh, *wkl, *wvh, *wvl;
    cudaGetSymbolAddress((void**)&xh,  g_xh);
    cudaGetSymbolAddress((void**)&xl,  g_xl);
    cudaGetSymbolAddress((void**)&wkh, g_wkh);
    cudaGetSymbolAddress((void**)&wkl, g_wkl);
    cudaGetSymbolAddress((void**)&wvh, g_wvh);
    cudaGetSymbolAddress((void**)&wvl, g_wvl);

    const int n4x = (M_DIM * D_DIM) / 4;
    const int n4w = (D_DIM * D_DIM) / 4;
    split_kernel<<<(n4x + 255) / 256, 256>>>(x,   xh,  xl,  n4x);
    split_kernel<<<(n4w + 255) / 256, 256>>>(W_k, wkh, wkl, n4w);
    split_kernel<<<(n4w + 255) / 256, 256>>>(W_v, wvh, wvl, n4w);

    cudaFuncSetAttribute(fused_gemm_kv,
                         cudaFuncAttributeMaxDynamicSharedMemorySize, SMEM_SZ);
    dim3 grid(D_DIM / BN, M_DIM / BM);            // (16, 256)
    fused_gemm_kv<<<grid, 256, SMEM_SZ>>>(b_k, b_v);

    scanA_kernel<<<(NSEG * BD) / 256, 256>>>();
    scanB_kernel<<<BD / 128, 128>>>(h0, out_h);
    scanC_kernel<<<(NSEG * BD) / 256, 256>>>(out_o, out_h);
}

// round 8
// speedup vs baseline: 1.2956x; 1.0647x over previous
#include <cuda_runtime.h>
#include <cuda_bf16.h>
#include <math.h>
#include <stdint.h>

// ---------------------------------------------------------------- constants
#define T_DIM 2048
#define B_DIM 16
#define D_DIM 1024
#define M_DIM (T_DIM * B_DIM)     // 32768
#define BD    (B_DIM * D_DIM)     // 16384
#define NSEG  16
#define SEGT  (T_DIM / NSEG)      // 128

// ---------------------------------------------------------------- scratch
__device__ float g_k[(size_t)M_DIM * D_DIM];              // sigmoid gate
__device__ float g_v[(size_t)M_DIM * D_DIM];              // tanh value
__device__ __nv_bfloat16 g_xh[(size_t)M_DIM * D_DIM];
__device__ __nv_bfloat16 g_xl[(size_t)M_DIM * D_DIM];
__device__ __nv_bfloat16 g_wkh[(size_t)D_DIM * D_DIM];
__device__ __nv_bfloat16 g_wkl[(size_t)D_DIM * D_DIM];
__device__ __nv_bfloat16 g_wvh[(size_t)D_DIM * D_DIM];
__device__ __nv_bfloat16 g_wvl[(size_t)D_DIM * D_DIM];
__device__ float g_segA[NSEG * BD];
__device__ float g_segB[NSEG * BD];
__device__ float g_hstart[NSEG * BD];

__device__ __forceinline__ float fast_sigmoid(float x) {
    return 1.0f / (1.0f + __expf(-x));
}

__device__ __forceinline__ uint32_t smem_u32(const void* p) {
    uint32_t a;
    asm("{ .reg .u64 t; cvta.to.shared.u64 t, %1; cvt.u32.u64 %0, t; }"
        : "=r"(a) : "l"(p));
    return a;
}

// ---------------------------------------------------------------- split
__global__ __launch_bounds__(256)
void split_kernel(const float* __restrict__ src,
                  __nv_bfloat16* __restrict__ hi,
                  __nv_bfloat16* __restrict__ lo, int n4)
{
    int i = blockIdx.x * 256 + threadIdx.x;
    if (i >= n4) return;
    float4 f = ((const float4*)src)[i];
    union { __nv_bfloat16 h[4]; unsigned long long u; } H, L;
    H.h[0] = __float2bfloat16(f.x);
    H.h[1] = __float2bfloat16(f.y);
    H.h[2] = __float2bfloat16(f.z);
    H.h[3] = __float2bfloat16(f.w);
    L.h[0] = __float2bfloat16(f.x - __bfloat162float(H.h[0]));
    L.h[1] = __float2bfloat16(f.y - __bfloat162float(H.h[1]));
    L.h[2] = __float2bfloat16(f.z - __bfloat162float(H.h[2]));
    L.h[3] = __float2bfloat16(f.w - __bfloat162float(H.h[3]));
    ((unsigned long long*)hi)[i] = H.u;
    ((unsigned long long*)lo)[i] = L.u;
}

// ---------------------------------------------------------------- fused GEMM
// 2 CTAs/SM, 256 threads, tile BM=128 x BN=64, BOTH outputs.
// NEW schedule: plane-interleaved chunks. Each chunk covers 32 k-positions
// with hi|lo planes CONCATENATED per smem row:
//   A row r: [Ah(64B) | Al(64B) | pad16]    (ROWB = 144)
//   W row r: [Wh(64B) | Wl(64B) | pad16]
// Per k16 step: MMA Ah*Wh + Al*Wh (reuse b regs), then Ah*Wl.
// Ah/Wh now fetched from gmem ONCE (was twice): -33% load & LDSM traffic,
// 32 chunks (was 48) -> fewer barriers. Same arithmetic, same accuracy.
static constexpr int BM = 128, BN = 64, KCH = 32;    // 32 k-positions per chunk
static constexpr int NCH = D_DIM / KCH;              // 32 chunks
static constexpr int ROWB = 2 * KCH * 2 + 16;        // 144 B (hi|lo|pad)
static constexpr int A_ST = BM * ROWB;               // 18432 B (A tile)
static constexpr int W_ST = BN * ROWB;               // 9216 B  (per W tile)
static constexpr int STAGE = A_ST + 2 * W_ST;        // 36864 B
static constexpr int NSTG = 3;
static constexpr int SMEM_SZ = NSTG * STAGE;         // 110592 B

#define CP_ASYNC16(dst, src) \
    asm volatile("cp.async.cg.shared.global [%0], [%1], 16;" :: "r"(dst), "l"(src))
#define CP_COMMIT() asm volatile("cp.async.commit_group;" ::: "memory")
#define CP_WAIT1()  asm volatile("cp.async.wait_group 1;" ::: "memory")

#define LDSM_X4(r0, r1, r2, r3, addr) \
    asm volatile("ldmatrix.sync.aligned.m8n8.x4.shared.b16 {%0,%1,%2,%3}, [%4];" \
                 : "=r"(r0), "=r"(r1), "=r"(r2), "=r"(r3) : "r"(addr))

#define MMA_BF16(d, a, b) \
    asm volatile("mma.sync.aligned.m16n8k16.row.col.f32.bf16.bf16.f32 " \
                 "{%0,%1,%2,%3}, {%4,%5,%6,%7}, {%8,%9}, {%0,%1,%2,%3};" \
                 : "+f"((d)[0]), "+f"((d)[1]), "+f"((d)[2]), "+f"((d)[3]) \
                 : "r"((a)[0]), "r"((a)[1]), "r"((a)[2]), "r"((a)[3]),   \
                   "r"((b)[0]), "r"((b)[1]))

__global__ __launch_bounds__(256, 2)
void fused_gemm_kv(const float* __restrict__ bk, const float* __restrict__ bv)
{
    extern __shared__ char smem[];
    const uint32_t sb = smem_u32(smem);
    const int tid = threadIdx.x;
    const int wid = tid >> 5;          // 0..7
    const int lid = tid & 31;
    const int bm = blockIdx.y * BM;
    const int bn = blockIdx.x * BN;

    const int wm0 = (wid & 3) * 32;    // 0..96
    const int wn0 = (wid >> 2) * 32;   // 0 or 32

    float acc[2][2][4][4];
    #pragma unroll
    for (int o = 0; o < 2; ++o)
        #pragma unroll
        for (int i = 0; i < 2; ++i)
            #pragma unroll
            for (int j = 0; j < 4; ++j)
                #pragma unroll
                for (int r = 0; r < 4; ++r) acc[o][i][j][r] = 0.0f;

    // per-thread ldmatrix address components (ROWB=144: conflict-free,
    // row bank offset = 36 mod 32 = 4 -> 8 rows hit 8 distinct bank groups)
    const uint32_t a_row_off = (uint32_t)(wm0 + (lid & 15)) * ROWB + (lid >> 4) * 16;
    const uint32_t b_row_off = (uint32_t)(wn0 + (lid & 7) + ((lid >> 4) & 1) * 8) * ROWB
                             + ((lid >> 3) & 1) * 16;

    // cp.async: 2048 16B-chunks per stage (A:1024, W:1024); 8 per thread.
    // Row layout: bytes [0,64) = hi plane k-slab, [64,128) = lo plane.
    auto issue_load = [&](int chunk, int buf) {
        const int kk = chunk * KCH;
        const uint32_t base = sb + buf * STAGE;
        // A tile: idx 0..1023 -> (row, 16B col); col<4 from xh, col>=4 from xl
        #pragma unroll
        for (int j = 0; j < 4; ++j) {
            const int idx = tid + j * 256;
            const int r = idx >> 3, cc = idx & 7;
            const __nv_bfloat16* src = (cc < 4)
                ? g_xh + (size_t)(bm + r) * D_DIM + kk + cc * 8
                : g_xl + (size_t)(bm + r) * D_DIM + kk + (cc - 4) * 8;
            CP_ASYNC16(base + r * ROWB + cc * 16, src);
        }
        // W tiles: idx 0..1023 -> (w, row, 16B col)
        #pragma unroll
        for (int j = 0; j < 4; ++j) {
            const int idx = tid + j * 256;
            const int w = idx >> 9;                // 0 = Wk, 1 = Wv
            const int r = (idx >> 3) & 63, cc = idx & 7;
            const __nv_bfloat16* hp_ = w ? g_wvh : g_wkh;
            const __nv_bfloat16* lp_ = w ? g_wvl : g_wkl;
            const __nv_bfloat16* src = (cc < 4)
                ? hp_ + (size_t)(bn + r) * D_DIM + kk + cc * 8
                : lp_ + (size_t)(bn + r) * D_DIM + kk + (cc - 4) * 8;
            CP_ASYNC16(base + A_ST + w * W_ST + r * ROWB + cc * 16, src);
        }
    };

    issue_load(0, 0); CP_COMMIT();
    issue_load(1, 1); CP_COMMIT();

    int buf_c = 0, buf_n = 2;
    for (int c = 0; c < NCH; ++c) {
        CP_WAIT1();
        __syncthreads();
        // safe: buffer buf_n == (c-1)%3 finished being read before the barrier
        if (c + 2 < NCH) issue_load(c + 2, buf_n);
        CP_COMMIT();

        const uint32_t Ab = sb + buf_c * STAGE;
        buf_n = buf_c;
        buf_c = (buf_c + 1 == 3) ? 0 : buf_c + 1;

        #pragma unroll
        for (int s = 0; s < 2; ++s) {              // two k16 steps per chunk
            // A fragments: hi and lo planes (lo at byte offset +64)
            uint32_t ah[2][4], al[2][4];
            #pragma unroll
            for (int mf = 0; mf < 2; ++mf) {
                const uint32_t base = Ab + a_row_off + (uint32_t)mf * 16 * ROWB + s * 32;
                LDSM_X4(ah[mf][0], ah[mf][1], ah[mf][2], ah[mf][3], base);
                LDSM_X4(al[mf][0], al[mf][1], al[mf][2], al[mf][3], base + 64);
            }
            uint32_t b[2][4][2];
            // --- plane hi of W: Ah*Wh + Al*Wh ---
            #pragma unroll
            for (int o = 0; o < 2; ++o) {
                const uint32_t Bb = Ab + A_ST + o * W_ST;
                #pragma unroll
                for (int nf2 = 0; nf2 < 2; ++nf2) {
                    uint32_t addr = Bb + b_row_off + (uint32_t)nf2 * 16 * ROWB + s * 32;
                    LDSM_X4(b[o][nf2 * 2][0], b[o][nf2 * 2][1],
                            b[o][nf2 * 2 + 1][0], b[o][nf2 * 2 + 1][1], addr);
                }
            }
            #pragma unroll
            for (int o = 0; o < 2; ++o)
                #pragma unroll
                for (int mf = 0; mf < 2; ++mf)
                    #pragma unroll
                    for (int nf = 0; nf < 4; ++nf) {
                        MMA_BF16(acc[o][mf][nf], ah[mf], b[o][nf]);
                        MMA_BF16(acc[o][mf][nf], al[mf], b[o][nf]);
                    }
            // --- plane lo of W: Ah*Wl (reuse b registers) ---
            #pragma unroll
            for (int o = 0; o < 2; ++o) {
                const uint32_t Bb = Ab + A_ST + o * W_ST;
                #pragma unroll
                for (int nf2 = 0; nf2 < 2; ++nf2) {
                    uint32_t addr = Bb + b_row_off + (uint32_t)nf2 * 16 * ROWB
                                  + s * 32 + 64;
                    LDSM_X4(b[o][nf2 * 2][0], b[o][nf2 * 2][1],
                            b[o][nf2 * 2 + 1][0], b[o][nf2 * 2 + 1][1], addr);
                }
            }
            #pragma unroll
            for (int o = 0; o < 2; ++o)
                #pragma unroll
                for (int mf = 0; mf < 2; ++mf)
                    #pragma unroll
                    for (int nf = 0; nf < 4; ++nf)
                        MMA_BF16(acc[o][mf][nf], ah[mf], b[o][nf]);
        }
    }

    // epilogue: bias + activation, f32x2 stores
    const int grow = lid >> 2;
    const int gcol = (lid & 3) * 2;
    #pragma unroll
    for (int o = 0; o < 2; ++o) {
        float* dst = o ? g_v : g_k;
        const float* bias = o ? bv : bk;
        #pragma unroll
        for (int nf = 0; nf < 4; ++nf) {
            const int col = bn + wn0 + nf * 8 + gcol;
            const float b0 = bias[col], b1 = bias[col + 1];
            #pragma unroll
            for (int mf = 0; mf < 2; ++mf) {
                const int r0 = bm + wm0 + mf * 16 + grow;
                float z0 = acc[o][mf][nf][0] + b0;
                float z1 = acc[o][mf][nf][1] + b1;
                float z2 = acc[o][mf][nf][2] + b0;
                float z3 = acc[o][mf][nf][3] + b1;
                float2 lo_, hi_;
                if (o == 0) {
                    lo_ = make_float2(fast_sigmoid(z0), fast_sigmoid(z1));
                    hi_ = make_float2(fast_sigmoid(z2), fast_sigmoid(z3));
                } else {
                    lo_ = make_float2(tanhf(z0), tanhf(z1));
                    hi_ = make_float2(tanhf(z2), tanhf(z3));
                }
                *(float2*)(dst + (size_t)r0 * D_DIM + col)       = lo_;
                *(float2*)(dst + (size_t)(r0 + 8) * D_DIM + col) = hi_;
            }
        }
    }
}

// ---------------------------------------------------------------- seg scan
__global__ __launch_bounds__(256)
void scanA_kernel()
{
    const int idx = blockIdx.x * 256 + threadIdx.x;   // 0..NSEG*BD-1
    const int i = idx & (BD - 1);
    const int s = idx >> 14;                          // BD = 2^14
    const size_t base = (size_t)(s * SEGT) * BD + i;

    const float* __restrict__ kp = g_k + base;
    const float* __restrict__ vp = g_v + base;

    float A = 1.0f, B = 0.0f;
    constexpr int U = 8;
    float ka[U], va[U], kb[U], vb[U];
    #pragma unroll
    for (int u = 0; u < U; ++u) { ka[u] = kp[(size_t)u * BD]; va[u] = vp[(size_t)u * BD]; }

    for (int j0 = 0; j0 < SEGT; j0 += U) {
        if (j0 + U < SEGT) {
            #pragma unroll
            for (int u = 0; u < U; ++u) {
                kb[u] = kp[(size_t)(j0 + U + u) * BD];
                vb[u] = vp[(size_t)(j0 + U + u) * BD];
            }
        }
        #pragma unroll
        for (int u = 0; u < U; ++u) {
            const float om = 1.0f - ka[u];
            B = om * B + ka[u] * va[u];
            A = om * A;
        }
        #pragma unroll
        for (int u = 0; u < U; ++u) { ka[u] = kb[u]; va[u] = vb[u]; }
    }
    g_segA[idx] = A;
    g_segB[idx] = B;
}

__global__ __launch_bounds__(128)
void scanB_kernel(const float* __restrict__ h0, float* __restrict__ out_h)
{
    const int i = blockIdx.x * 128 + threadIdx.x;
    float h = h0[i];
    out_h[i] = h;
    #pragma unroll
    for (int s = 0; s < NSEG; ++s) {
        g_hstart[s * BD + i] = h;
        h = g_segA[s * BD + i] * h + g_segB[s * BD + i];
    }
}

__global__ __launch_bounds__(256)
void scanC_kernel(float* __restrict__ out_o, float* __restrict__ out_h)
{
    const int idx = blockIdx.x * 256 + threadIdx.x;
    const int i = idx & (BD - 1);
    const int s = idx >> 14;
    const int t0 = s * SEGT;
    const size_t base = (size_t)t0 * BD + i;

    const float* __restrict__ kp = g_k + base;
    const float* __restrict__ vp = g_v + base;
    float* __restrict__ op = out_o + base;
    float* __restrict__ hp = out_h + (size_t)BD + base;

    float h = g_hstart[s * BD + i];
    constexpr int U = 8;
    float ka[U], va[U], kb[U], vb[U];
    #pragma unroll
    for (int u = 0; u < U; ++u) { ka[u] = kp[(size_t)u * BD]; va[u] = vp[(size_t)u * BD]; }

    for (int j0 = 0; j0 < SEGT; j0 += U) {
        if (j0 + U < SEGT) {
            #pragma unroll
            for (int u = 0; u < U; ++u) {
                kb[u] = kp[(size_t)(j0 + U + u) * BD];
                vb[u] = vp[(size_t)(j0 + U + u) * BD];
            }
        }
        #pragma unroll
        for (int u = 0; u < U; ++u) {
            h = (1.0f - ka[u]) * h + ka[u] * va[u];
            hp[(size_t)(j0 + u) * BD] = h;
            float sg = fast_sigmoid(h);
            op[(size_t)(j0 + u) * BD] = h * h * sg;
        }
        #pragma unroll
        for (int u = 0; u < U; ++u) { ka[u] = kb[u]; va[u] = vb[u]; }
    }
}

// ---------------------------------------------------------------- launch
extern "C" void kernel_launch(void* const* d_in, const int* in_sizes, int n_in,
                              void* d_out, int out_size)
{
    const float* x   = (const float*)d_in[0];
    const float* h0  = (const float*)d_in[1];
    const float* W_k = (const float*)d_in[2];
    const float* b_k = (const float*)d_in[3];
    const float* W_v = (const float*)d_in[4];
    const float* b_v = (const float*)d_in[5];

    float* out   = (float*)d_out;
    float* out_o = out;                           // [T, B, D]
    float* out_h = out + (size_t)T_DIM * BD;      // [T+1, B, D]

    __nv_bfloat16 *xh, *xl, *wkh, *wkl, *wvh, *wvl;
    cudaGetSymbolAddress((void**)&xh,  g_xh);
    cudaGetSymbolAddress((void**)&xl,  g_xl);
    cudaGetSymbolAddress((void**)&wkh, g_wkh);
    cudaGetSymbolAddress((void**)&wkl, g_wkl);
    cudaGetSymbolAddress((void**)&wvh, g_wvh);
    cudaGetSymbolAddress((void**)&wvl, g_wvl);

    const int n4x = (M_DIM * D_DIM) / 4;
    const int n4w = (D_DIM * D_DIM) / 4;
    split_kernel<<<(n4x + 255) / 256, 256>>>(x,   xh,  xl,  n4x);
    split_kernel<<<(n4w + 255) / 256, 256>>>(W_k, wkh, wkl, n4w);
    split_kernel<<<(n4w + 255) / 256, 256>>>(W_v, wvh, wvl, n4w);

    cudaFuncSetAttribute(fused_gemm_kv,
                         cudaFuncAttributeMaxDynamicSharedMemorySize, SMEM_SZ);
    dim3 grid(D_DIM / BN, M_DIM / BM);            // (16, 256)
    fused_gemm_kv<<<grid, 256, SMEM_SZ>>>(b_k, b_v);

    scanA_kernel<<<(NSEG * BD) / 256, 256>>>();
    scanB_kernel<<<BD / 128, 128>>>(h0, out_h);
    scanC_kernel<<<(NSEG * BD) / 256, 256>>>(out_o, out_h);
}

// round 10
// speedup vs baseline: 1.4089x; 1.0875x over previous
#include <cuda_runtime.h>
#include <cuda_bf16.h>
#include <math.h>
#include <stdint.h>

// ---------------------------------------------------------------- constants
#define T_DIM 2048
#define B_DIM 16
#define D_DIM 1024
#define M_DIM (T_DIM * B_DIM)     // 32768
#define BD    (B_DIM * D_DIM)     // 16384
#define NSEG  16
#define SEGT  (T_DIM / NSEG)      // 128

// ---------------------------------------------------------------- scratch
__device__ float g_k[(size_t)M_DIM * D_DIM];              // sigmoid gate
__device__ float g_v[(size_t)M_DIM * D_DIM];              // tanh value
__device__ __nv_bfloat16 g_xh[(size_t)M_DIM * D_DIM];
__device__ __nv_bfloat16 g_xl[(size_t)M_DIM * D_DIM];
__device__ __nv_bfloat16 g_wkh[(size_t)D_DIM * D_DIM];
__device__ __nv_bfloat16 g_wkl[(size_t)D_DIM * D_DIM];
__device__ __nv_bfloat16 g_wvh[(size_t)D_DIM * D_DIM];
__device__ __nv_bfloat16 g_wvl[(size_t)D_DIM * D_DIM];
__device__ float g_segA[NSEG * BD];
__device__ float g_segB[NSEG * BD];
__device__ float g_hstart[NSEG * BD];

__device__ __forceinline__ float fast_sigmoid(float x) {
    return 1.0f / (1.0f + __expf(-x));
}

__device__ __forceinline__ uint32_t smem_u32(const void* p) {
    uint32_t a;
    asm("{ .reg .u64 t; cvta.to.shared.u64 t, %1; cvt.u32.u64 %0, t; }"
        : "=r"(a) : "l"(p));
    return a;
}

// ---------------------------------------------------------------- mbarrier
#define MBARRIER_INIT(addr, cnt) \
    asm volatile("mbarrier.init.shared.b64 [%0], %1;" :: "r"(addr), "r"(cnt) : "memory")

#define MBARRIER_ARRIVE(addr) \
    asm volatile("mbarrier.arrive.shared.b64 _, [%0];" :: "r"(addr) : "memory")

// arrive on mbarrier once this thread's prior cp.async ops complete.
// .noinc REQUIRED: default form is count-neutral (inc at issue, dec at done)
// and would never complete a phase fed only by cp.async arrivals (R9 hang).
#define CP_ASYNC_MBAR_ARRIVE_NOINC(addr) \
    asm volatile("cp.async.mbarrier.arrive.noinc.shared::cta.b64 [%0];" :: "r"(addr) : "memory")

#define MBARRIER_WAIT_PARITY(mbar, parity) do {                                   \
    uint32_t _m = (mbar); uint32_t _p = (parity); uint32_t _done;                 \
    asm volatile("{\n\t.reg .pred p;\n\t"                                         \
        "mbarrier.try_wait.parity.acquire.cta.shared::cta.b64 p, [%1], %2;\n\t"   \
        "selp.b32 %0, 1, 0, p;\n\t}"                                              \
        : "=r"(_done) : "r"(_m), "r"(_p) : "memory");                             \
    if (!_done) {                                                                 \
        asm volatile("{\n\t.reg .pred P1;\n\t"                                    \
            "WL_%=:\n\t"                                                          \
            "mbarrier.try_wait.parity.acquire.cta.shared::cta.b64 P1, [%0], %1, 0x989680;\n\t" \
            "@P1 bra.uni WD_%=;\n\t"                                              \
            "bra.uni WL_%=;\n\t"                                                  \
            "WD_%=:\n\t}"                                                         \
            :: "r"(_m), "r"(_p) : "memory");                                      \
    }                                                                             \
} while (0)

// ---------------------------------------------------------------- split
__global__ __launch_bounds__(256)
void split_kernel(const float* __restrict__ src,
                  __nv_bfloat16* __restrict__ hi,
                  __nv_bfloat16* __restrict__ lo, int n4)
{
    int i = blockIdx.x * 256 + threadIdx.x;
    if (i >= n4) return;
    float4 f = ((const float4*)src)[i];
    union { __nv_bfloat16 h[4]; unsigned long long u; } H, L;
    H.h[0] = __float2bfloat16(f.x);
    H.h[1] = __float2bfloat16(f.y);
    H.h[2] = __float2bfloat16(f.z);
    H.h[3] = __float2bfloat16(f.w);
    L.h[0] = __float2bfloat16(f.x - __bfloat162float(H.h[0]));
    L.h[1] = __float2bfloat16(f.y - __bfloat162float(H.h[1]));
    L.h[2] = __float2bfloat16(f.z - __bfloat162float(H.h[2]));
    L.h[3] = __float2bfloat16(f.w - __bfloat162float(H.h[3]));
    ((unsigned long long*)hi)[i] = H.u;
    ((unsigned long long*)lo)[i] = L.u;
}

// ---------------------------------------------------------------- fused GEMM
// Warp-specialized producer/consumer, 2 CTAs/SM, 288 threads:
//   warps 0-7: consumers (LDSM + MMA only), 4(m) x 2(n), tile 128x64, both outs
//   warp 8   : producer (all cp.async), mbarrier-paced, no __syncthreads
// Plane-interleaved chunks (R8 layout): row = [hi(64B) | lo(64B) | pad16].
static constexpr int BM = 128, BN = 64, KCH = 32;
static constexpr int NCH = D_DIM / KCH;              // 32 chunks
static constexpr int ROWB = 2 * KCH * 2 + 16;        // 144 B
static constexpr int A_ST = BM * ROWB;               // 18432 B
static constexpr int W_ST = BN * ROWB;               // 9216 B
static constexpr int STAGE = A_ST + 2 * W_ST;        // 36864 B
static constexpr int NSTG = 3;
static constexpr int MBAR_OFF = NSTG * STAGE;        // mbarriers after stages
static constexpr int SMEM_SZ = MBAR_OFF + 64;        // 110656 B (x2 CTA <= 227KB)

#define CP_ASYNC16(dst, src) \
    asm volatile("cp.async.cg.shared.global [%0], [%1], 16;" :: "r"(dst), "l"(src))

#define LDSM_X4(r0, r1, r2, r3, addr) \
    asm volatile("ldmatrix.sync.aligned.m8n8.x4.shared.b16 {%0,%1,%2,%3}, [%4];" \
                 : "=r"(r0), "=r"(r1), "=r"(r2), "=r"(r3) : "r"(addr))

#define MMA_BF16(d, a, b) \
    asm volatile("mma.sync.aligned.m16n8k16.row.col.f32.bf16.bf16.f32 " \
                 "{%0,%1,%2,%3}, {%4,%5,%6,%7}, {%8,%9}, {%0,%1,%2,%3};" \
                 : "+f"((d)[0]), "+f"((d)[1]), "+f"((d)[2]), "+f"((d)[3]) \
                 : "r"((a)[0]), "r"((a)[1]), "r"((a)[2]), "r"((a)[3]),   \
                   "r"((b)[0]), "r"((b)[1]))

__global__ __launch_bounds__(288, 2)
void fused_gemm_kv(const float* __restrict__ bk, const float* __restrict__ bv)
{
    extern __shared__ char smem[];
    const uint32_t sb = smem_u32(smem);
    const int tid = threadIdx.x;
    const int wid = tid >> 5;          // 0..8
    const int lid = tid & 31;
    const int bm = blockIdx.y * BM;
    const int bn = blockIdx.x * BN;

    // mbarriers: full[0..2] (count 32: one noinc-arrive per producer lane),
    //            empty[0..2] (count 8: one arrive per consumer warp)
    const uint32_t mb_full  = sb + MBAR_OFF;        // 3 x 8B
    const uint32_t mb_empty = sb + MBAR_OFF + 24;   // 3 x 8B
    if (tid == 0) {
        #pragma unroll
        for (int s = 0; s < NSTG; ++s) {
            MBARRIER_INIT(mb_full  + s * 8, 32);
            MBARRIER_INIT(mb_empty + s * 8, 8);
        }
    }
    __syncthreads();                                 // only CTA-wide sync

    if (wid == 8) {
        // ---------------- producer warp ----------------
        const int rA0 = lid >> 3;                    // 0..3
        const int cc  = lid & 7;                     // fixed 16B column
        const int gcol = (cc < 4 ? cc : cc - 4) * 8; // bf16 col in plane
        const bool hiP = (cc < 4);
        int st = 0, ph = 1;                          // first empty-waits pass
        for (int c = 0; c < NCH; ++c) {
            MBARRIER_WAIT_PARITY(mb_empty + st * 8, ph);
            const int kk = c * KCH;
            const uint32_t base = sb + st * STAGE;
            // A tile: rows 0..127, this lane covers rows rA0+4j
            const __nv_bfloat16* Aplane = hiP ? g_xh : g_xl;
            #pragma unroll
            for (int j = 0; j < 32; ++j) {
                const int r = j * 4 + rA0;
                CP_ASYNC16(base + r * ROWB + cc * 16,
                           Aplane + (size_t)(bm + r) * D_DIM + kk + gcol);
            }
            // W tiles: logical rows 0..127 -> Wk rows 0..63, Wv rows 0..63
            #pragma unroll
            for (int j = 0; j < 32; ++j) {
                const int rw = j * 4 + rA0;          // 0..127
                const int w = rw >> 6;               // 0 = Wk, 1 = Wv
                const int r = rw & 63;
                const __nv_bfloat16* Wplane = w
                    ? (hiP ? g_wvh : g_wvl)
                    : (hiP ? g_wkh : g_wkl);
                CP_ASYNC16(base + A_ST + w * W_ST + r * ROWB + cc * 16,
                           Wplane + (size_t)(bn + r) * D_DIM + kk + gcol);
            }
            CP_ASYNC_MBAR_ARRIVE_NOINC(mb_full + st * 8);
            if (++st == NSTG) { st = 0; ph ^= 1; }
        }
        return;                                      // producer done
    }

    // ---------------- consumer warps (0..7) ----------------
    const int wm0 = (wid & 3) * 32;
    const int wn0 = (wid >> 2) * 32;

    float acc[2][2][4][4];
    #pragma unroll
    for (int o = 0; o < 2; ++o)
        #pragma unroll
        for (int i = 0; i < 2; ++i)
            #pragma unroll
            for (int j = 0; j < 4; ++j)
                #pragma unroll
                for (int r = 0; r < 4; ++r) acc[o][i][j][r] = 0.0f;

    const uint32_t a_row_off = (uint32_t)(wm0 + (lid & 15)) * ROWB + (lid >> 4) * 16;
    const uint32_t b_row_off = (uint32_t)(wn0 + (lid & 7) + ((lid >> 4) & 1) * 8) * ROWB
                             + ((lid >> 3) & 1) * 16;

    int st = 0, ph = 0;
    for (int c = 0; c < NCH; ++c) {
        MBARRIER_WAIT_PARITY(mb_full + st * 8, ph);
        const uint32_t Ab = sb + st * STAGE;

        #pragma unroll
        for (int s = 0; s < 2; ++s) {                // two k16 steps
            uint32_t ah[2][4], al[2][4];
            #pragma unroll
            for (int mf = 0; mf < 2; ++mf) {
                const uint32_t base = Ab + a_row_off + (uint32_t)mf * 16 * ROWB + s * 32;
                LDSM_X4(ah[mf][0], ah[mf][1], ah[mf][2], ah[mf][3], base);
                LDSM_X4(al[mf][0], al[mf][1], al[mf][2], al[mf][3], base + 64);
            }
            uint32_t b[2][4][2];
            // plane hi of W: Ah*Wh + Al*Wh
            #pragma unroll
            for (int o = 0; o < 2; ++o) {
                const uint32_t Bb = Ab + A_ST + o * W_ST;
                #pragma unroll
                for (int nf2 = 0; nf2 < 2; ++nf2) {
                    uint32_t addr = Bb + b_row_off + (uint32_t)nf2 * 16 * ROWB + s * 32;
                    LDSM_X4(b[o][nf2 * 2][0], b[o][nf2 * 2][1],
                            b[o][nf2 * 2 + 1][0], b[o][nf2 * 2 + 1][1], addr);
                }
            }
            #pragma unroll
            for (int o = 0; o < 2; ++o)
                #pragma unroll
                for (int mf = 0; mf < 2; ++mf)
                    #pragma unroll
                    for (int nf = 0; nf < 4; ++nf) {
                        MMA_BF16(acc[o][mf][nf], ah[mf], b[o][nf]);
                        MMA_BF16(acc[o][mf][nf], al[mf], b[o][nf]);
                    }
            // plane lo of W: Ah*Wl (reuse b regs)
            #pragma unroll
            for (int o = 0; o < 2; ++o) {
                const uint32_t Bb = Ab + A_ST + o * W_ST;
                #pragma unroll
                for (int nf2 = 0; nf2 < 2; ++nf2) {
                    uint32_t addr = Bb + b_row_off + (uint32_t)nf2 * 16 * ROWB
                                  + s * 32 + 64;
                    LDSM_X4(b[o][nf2 * 2][0], b[o][nf2 * 2][1],
                            b[o][nf2 * 2 + 1][0], b[o][nf2 * 2 + 1][1], addr);
                }
            }
            #pragma unroll
            for (int o = 0; o < 2; ++o)
                #pragma unroll
                for (int mf = 0; mf < 2; ++mf)
                    #pragma unroll
                    for (int nf = 0; nf < 4; ++nf)
                        MMA_BF16(acc[o][mf][nf], ah[mf], b[o][nf]);
        }

        __syncwarp();
        if (lid == 0) MBARRIER_ARRIVE(mb_empty + st * 8);   // release
        if (++st == NSTG) { st = 0; ph ^= 1; }
    }

    // epilogue: bias + activation, f32x2 stores (per-warp, no CTA sync)
    const int grow = lid >> 2;
    const int gcol = (lid & 3) * 2;
    #pragma unroll
    for (int o = 0; o < 2; ++o) {
        float* dst = o ? g_v : g_k;
        const float* bias = o ? bv : bk;
        #pragma unroll
        for (int nf = 0; nf < 4; ++nf) {
            const int col = bn + wn0 + nf * 8 + gcol;
            const float b0 = bias[col], b1 = bias[col + 1];
            #pragma unroll
            for (int mf = 0; mf < 2; ++mf) {
                const int r0 = bm + wm0 + mf * 16 + grow;
                float z0 = acc[o][mf][nf][0] + b0;
                float z1 = acc[o][mf][nf][1] + b1;
                float z2 = acc[o][mf][nf][2] + b0;
                float z3 = acc[o][mf][nf][3] + b1;
                float2 lo_, hi_;
                if (o == 0) {
                    lo_ = make_float2(fast_sigmoid(z0), fast_sigmoid(z1));
                    hi_ = make_float2(fast_sigmoid(z2), fast_sigmoid(z3));
                } else {
                    lo_ = make_float2(tanhf(z0), tanhf(z1));
                    hi_ = make_float2(tanhf(z2), tanhf(z3));
                }
                *(float2*)(dst + (size_t)r0 * D_DIM + col)       = lo_;
                *(float2*)(dst + (size_t)(r0 + 8) * D_DIM + col) = hi_;
            }
        }
    }
}

// ---------------------------------------------------------------- seg scan
__global__ __launch_bounds__(256)
void scanA_kernel()
{
    const int idx = blockIdx.x * 256 + threadIdx.x;   // 0..NSEG*BD-1
    const int i = idx & (BD - 1);
    const int s = idx >> 14;                          // BD = 2^14
    const size_t base = (size_t)(s * SEGT) * BD + i;

    const float* __restrict__ kp = g_k + base;
    const float* __restrict__ vp = g_v + base;

    float A = 1.0f, B = 0.0f;
    constexpr int U = 8;
    float ka[U], va[U], kb[U], vb[U];
    #pragma unroll
    for (int u = 0; u < U; ++u) { ka[u] = kp[(size_t)u * BD]; va[u] = vp[(size_t)u * BD]; }

    for (int j0 = 0; j0 < SEGT; j0 += U) {
        if (j0 + U < SEGT) {
            #pragma unroll
            for (int u = 0; u < U; ++u) {
                kb[u] = kp[(size_t)(j0 + U + u) * BD];
                vb[u] = vp[(size_t)(j0 + U + u) * BD];
            }
        }
        #pragma unroll
        for (int u = 0; u < U; ++u) {
            const float om = 1.0f - ka[u];
            B = om * B + ka[u] * va[u];
            A = om * A;
        }
        #pragma unroll
        for (int u = 0; u < U; ++u) { ka[u] = kb[u]; va[u] = vb[u]; }
    }
    g_segA[idx] = A;
    g_segB[idx] = B;
}

__global__ __launch_bounds__(128)
void scanB_kernel(const float* __restrict__ h0, float* __restrict__ out_h)
{
    const int i = blockIdx.x * 128 + threadIdx.x;
    float h = h0[i];
    out_h[i] = h;
    #pragma unroll
    for (int s = 0; s < NSEG; ++s) {
        g_hstart[s * BD + i] = h;
        h = g_segA[s * BD + i] * h + g_segB[s * BD + i];
    }
}

__global__ __launch_bounds__(256)
void scanC_kernel(float* __restrict__ out_o, float* __restrict__ out_h)
{
    const int idx = blockIdx.x * 256 + threadIdx.x;
    const int i = idx & (BD - 1);
    const int s = idx >> 14;
    const int t0 = s * SEGT;
    const size_t base = (size_t)t0 * BD + i;

    const float* __restrict__ kp = g_k + base;
    const float* __restrict__ vp = g_v + base;
    float* __restrict__ op = out_o + base;
    float* __restrict__ hp = out_h + (size_t)BD + base;

    float h = g_hstart[s * BD + i];
    constexpr int U = 8;
    float ka[U], va[U], kb[U], vb[U];
    #pragma unroll
    for (int u = 0; u < U; ++u) { ka[u] = kp[(size_t)u * BD]; va[u] = vp[(size_t)u * BD]; }

    for (int j0 = 0; j0 < SEGT; j0 += U) {
        if (j0 + U < SEGT) {
            #pragma unroll
            for (int u = 0; u < U; ++u) {
                kb[u] = kp[(size_t)(j0 + U + u) * BD];
                vb[u] = vp[(size_t)(j0 + U + u) * BD];
            }
        }
        #pragma unroll
        for (int u = 0; u < U; ++u) {
            h = (1.0f - ka[u]) * h + ka[u] * va[u];
            hp[(size_t)(j0 + u) * BD] = h;
            float sg = fast_sigmoid(h);
            op[(size_t)(j0 + u) * BD] = h * h * sg;
        }
        #pragma unroll
        for (int u = 0; u < U; ++u) { ka[u] = kb[u]; va[u] = vb[u]; }
    }
}

// ---------------------------------------------------------------- launch
extern "C" void kernel_launch(void* const* d_in, const int* in_sizes, int n_in,
                              void* d_out, int out_size)
{
    const float* x   = (const float*)d_in[0];
    const float* h0  = (const float*)d_in[1];
    const float* W_k = (const float*)d_in[2];
    const float* b_k = (const float*)d_in[3];
    const float* W_v = (const float*)d_in[4];
    const float* b_v = (const float*)d_in[5];

    float* out   = (float*)d_out;
    float* out_o = out;                           // [T, B, D]
    float* out_h = out + (size_t)T_DIM * BD;      // [T+1, B, D]

    __nv_bfloat16 *xh, *xl, *wkh, *wkl, *wvh, *wvl;
    cudaGetSymbolAddress((void**)&xh,  g_xh);
    cudaGetSymbolAddress((void**)&xl,  g_xl);
    cudaGetSymbolAddress((void**)&wkh, g_wkh);
    cudaGetSymbolAddress((void**)&wkl, g_wkl);
    cudaGetSymbolAddress((void**)&wvh, g_wvh);
    cudaGetSymbolAddress((void**)&wvl, g_wvl);

    const int n4x = (M_DIM * D_DIM) / 4;
    const int n4w = (D_DIM * D_DIM) / 4;
    split_kernel<<<(n4x + 255) / 256, 256>>>(x,   xh,  xl,  n4x);
    split_kernel<<<(n4w + 255) / 256, 256>>>(W_k, wkh, wkl, n4w);
    split_kernel<<<(n4w + 255) / 256, 256>>>(W_v, wvh, wvl, n4w);

    cudaFuncSetAttribute(fused_gemm_kv,
                         cudaFuncAttributeMaxDynamicSharedMemorySize, SMEM_SZ);
    dim3 grid(D_DIM / BN, M_DIM / BM);            // (16, 256)
    fused_gemm_kv<<<grid, 288, SMEM_SZ>>>(b_k, b_v);

    scanA_kernel<<<(NSEG * BD) / 256, 256>>>();
    scanB_kernel<<<BD / 128, 128>>>(h0, out_h);
    scanC_kernel<<<(NSEG * BD) / 256, 256>>>(out_o, out_h);
}